// round 1
// baseline (speedup 1.0000x reference)
#include <cuda_runtime.h>
#include <cuda_bf16.h>
#include <mma.h>
#include <cstdint>

using namespace nvcuda;

// ---------------- Problem constants ----------------
#define TT 4
#define BB 16
#define CC 512
#define HH 16
#define WW 16
#define NN 256            // H*W tokens
#define NHEAD 8
#define DH 64             // head dim
#define HID 2048          // 4*C
#define MROWS (TT*BB*NN)  // 16384
#define BNROWS (BB*NN)    // 4096
#define PLANE (BB*CC*HH*WW) // 2097152 (per-t x plane)

// ---------------- Static device scratch (no cudaMalloc allowed) ----------------
__device__ float          g_xt  [(size_t)MROWS*CC];      // token stream [T,B,N,C]
__device__ float          g_qkv [(size_t)MROWS*3*CC];    // qkv pre-activations
__device__ float          g_ff  [(size_t)MROWS*HID];     // fc1 out; also reused as conv-out y (NCHW) early
__device__ float          g_a   [(size_t)MROWS*CC];      // attention output (pre-LIF)
__device__ float          g_tmp [(size_t)MROWS*CC];      // proj out / fc2 out
__device__ float          g_kv  [(size_t)TT*BB*NHEAD*DH*DH];
__device__ unsigned char  g_s1  [(size_t)TT*PLANE];      // spikes of lif(x)
__device__ unsigned char  g_q   [(size_t)TT*BB*NHEAD*NN*DH];
__device__ unsigned char  g_k   [(size_t)TT*BB*NHEAD*NN*DH];
__device__ unsigned char  g_v   [(size_t)TT*BB*NHEAD*NN*DH];
__device__ __nv_bfloat16  g_h   [(size_t)MROWS*CC];      // spike GEMM-LHS (h1 / a-spikes / h3)
__device__ __nv_bfloat16  g_h4  [(size_t)MROWS*HID];     // MLP spike LHS
__device__ __nv_bfloat16  g_wq  [(size_t)3*CC*CC];
__device__ __nv_bfloat16  g_wp  [(size_t)CC*CC];
__device__ __nv_bfloat16  g_w1  [(size_t)HID*CC];
__device__ __nv_bfloat16  g_w2  [(size_t)CC*HID];

// ---------------- helpers ----------------
__device__ __forceinline__ float sigmoidf_(float w){ return 1.f/(1.f+expf(-w)); }

// ---------------- weight -> bf16 ----------------
__global__ void k_cvt_bf16(const float* __restrict__ s, __nv_bfloat16* __restrict__ d, int n){
    int i = blockIdx.x*blockDim.x + threadIdx.x;
    if (i < n) d[i] = __float2bfloat16(s[i]);
}

// ---------------- LIF over T on raw input x -> u8 spikes ----------------
__global__ void k_lif1(const float* __restrict__ x, const float* __restrict__ lw,
                       unsigned char* __restrict__ s1){
    int i = blockIdx.x*blockDim.x + threadIdx.x;
    if (i >= PLANE) return;
    float decay = sigmoidf_(lw[0]);
    float v = 0.f;
#pragma unroll
    for (int t = 0; t < TT; t++){
        v += (x[(size_t)t*PLANE + i] - v)*decay;
        unsigned char s = (v >= 1.f);
        s1[(size_t)t*PLANE + i] = s;
        if (s) v = 0.f;
    }
}

// ---------------- depthwise 3x3 conv on spikes + residual (NCHW layout) ----------------
__global__ void k_conv(const float* __restrict__ x, const unsigned char* __restrict__ s1,
                       const float* __restrict__ cw, const float* __restrict__ cb,
                       float* __restrict__ y){
    int i = blockIdx.x*blockDim.x + threadIdx.x;
    if (i >= TT*PLANE) return;
    int w = i & 15, h = (i>>4) & 15, c = (i>>8) & 511;
    int base = i - (h*16 + w);                 // start of this (tb,c) plane
    float acc = cb[c];
    const float* wk = cw + c*9;
#pragma unroll
    for (int dy = -1; dy <= 1; dy++){
        int hh = h + dy; if ((unsigned)hh >= 16u) continue;
#pragma unroll
        for (int dx = -1; dx <= 1; dx++){
            int ww = w + dx; if ((unsigned)ww >= 16u) continue;
            acc += wk[(dy+1)*3 + (dx+1)] * (float)s1[base + hh*16 + ww];
        }
    }
    y[i] = x[i] + acc;
}

// ---------------- transpose [tb][C][N] -> [tb][N][C] ----------------
__global__ void k_transpose(const float* __restrict__ y, float* __restrict__ xt){
    __shared__ float tile[32][33];
    int tb = blockIdx.z;
    int c0 = blockIdx.y*32, n0 = blockIdx.x*32;
    int tx = threadIdx.x, ty = threadIdx.y;
    const float* src = y + (size_t)tb*CC*NN;
    float* dst = xt + (size_t)tb*NN*CC;
#pragma unroll
    for (int j = 0; j < 32; j += 8)
        tile[ty+j][tx] = src[(size_t)(c0+ty+j)*NN + n0+tx];
    __syncthreads();
#pragma unroll
    for (int j = 0; j < 32; j += 8)
        dst[(size_t)(n0+ty+j)*CC + c0+tx] = tile[tx][ty+j];
}

// ---------------- (optional residual add) + LayerNorm(C) + LIF over T -> bf16 spikes ----------------
__global__ void __launch_bounds__(256) k_ln_lif(
        float* __restrict__ xt, const float* __restrict__ g, const float* __restrict__ bvec,
        const float* __restrict__ lw, int lwi,
        const float* __restrict__ addsrc, const float* __restrict__ abias,
        __nv_bfloat16* __restrict__ hout){
    int bn  = blockIdx.x;        // 0..4095 over (b,n)
    int tid = threadIdx.x;       // 256 threads, each handles 2 channels
    int c0 = tid, c1 = tid + 256;
    float decay = sigmoidf_(lw[lwi]);
    float g0 = g[c0], g1 = g[c1], b0 = bvec[c0], b1 = bvec[c1];
    float ab0 = 0.f, ab1 = 0.f;
    if (abias){ ab0 = abias[c0]; ab1 = abias[c1]; }
    __shared__ float ssum[256], ssq[256];
    float v0 = 0.f, v1 = 0.f;
    for (int t = 0; t < TT; t++){
        size_t base = ((size_t)t*BNROWS + bn)*CC;
        float x0 = xt[base + c0], x1 = xt[base + c1];
        if (addsrc){
            x0 += addsrc[base + c0] + ab0;
            x1 += addsrc[base + c1] + ab1;
            xt[base + c0] = x0; xt[base + c1] = x1;
        }
        ssum[tid] = x0 + x1; ssq[tid] = x0*x0 + x1*x1;
        __syncthreads();
        for (int o = 128; o > 0; o >>= 1){
            if (tid < o){ ssum[tid] += ssum[tid+o]; ssq[tid] += ssq[tid+o]; }
            __syncthreads();
        }
        float mean = ssum[0]*(1.f/512.f);
        float var  = ssq[0]*(1.f/512.f) - mean*mean;
        __syncthreads();
        float rstd = rsqrtf(var + 1e-5f);
        float y0 = (x0 - mean)*rstd*g0 + b0;
        float y1 = (x1 - mean)*rstd*g1 + b1;
        v0 += (y0 - v0)*decay; v1 += (y1 - v1)*decay;
        float s0 = (v0 >= 1.f) ? 1.f : 0.f;
        float s1v = (v1 >= 1.f) ? 1.f : 0.f;
        hout[base + c0] = __float2bfloat16(s0);
        hout[base + c1] = __float2bfloat16(s1v);
        if (s0 > 0.f) v0 = 0.f;
        if (s1v > 0.f) v1 = 0.f;
    }
}

// ---------------- bf16 WMMA GEMM: C[M,N] = A[M,K] @ W[N,K]^T (fp32 accum) ----------------
#define GBM 128
#define GBN 128
#define GBK 32
#define GPAD 48   // padded row stride (elems): 96B rows -> 32B-aligned fragment ptrs

__global__ void __launch_bounds__(256) k_gemm_bf16(
        const __nv_bfloat16* __restrict__ A, const __nv_bfloat16* __restrict__ W,
        float* __restrict__ C, int M, int N, int K){
    __shared__ __nv_bfloat16 sA[GBM][GPAD];
    __shared__ __nv_bfloat16 sB[GBN][GPAD];
    int tid = threadIdx.x;
    int bm = blockIdx.y * GBM;
    int bn = blockIdx.x * GBN;
    int warp = tid >> 5;
    int wm = warp >> 2, wn = warp & 3;   // 2 x 4 warp grid, warp tile 64x32

    wmma::fragment<wmma::accumulator,16,16,16,float> acc[4][2];
#pragma unroll
    for (int i = 0; i < 4; i++)
#pragma unroll
        for (int j = 0; j < 2; j++) wmma::fill_fragment(acc[i][j], 0.f);

    int lrow = tid >> 1, lcol = (tid & 1) * 16;
    for (int k0 = 0; k0 < K; k0 += GBK){
        const __nv_bfloat16* sa = A + (size_t)(bm + lrow)*K + k0 + lcol;
        const __nv_bfloat16* sb = W + (size_t)(bn + lrow)*K + k0 + lcol;
        *(uint4*)&sA[lrow][lcol]     = *(const uint4*)sa;
        *(uint4*)&sA[lrow][lcol + 8] = *(const uint4*)(sa + 8);
        *(uint4*)&sB[lrow][lcol]     = *(const uint4*)sb;
        *(uint4*)&sB[lrow][lcol + 8] = *(const uint4*)(sb + 8);
        __syncthreads();
#pragma unroll
        for (int ks = 0; ks < GBK; ks += 16){
            wmma::fragment<wmma::matrix_a,16,16,16,__nv_bfloat16,wmma::row_major> af[4];
            wmma::fragment<wmma::matrix_b,16,16,16,__nv_bfloat16,wmma::col_major> bf[2];
#pragma unroll
            for (int i = 0; i < 4; i++)
                wmma::load_matrix_sync(af[i], &sA[wm*64 + i*16][ks], GPAD);
#pragma unroll
            for (int j = 0; j < 2; j++)
                wmma::load_matrix_sync(bf[j], &sB[wn*32 + j*16][ks], GPAD);
#pragma unroll
            for (int i = 0; i < 4; i++)
#pragma unroll
                for (int j = 0; j < 2; j++)
                    wmma::mma_sync(acc[i][j], af[i], bf[j], acc[i][j]);
        }
        __syncthreads();
    }
#pragma unroll
    for (int i = 0; i < 4; i++)
#pragma unroll
        for (int j = 0; j < 2; j++)
            wmma::store_matrix_sync(&C[(size_t)(bm + wm*64 + i*16)*N + bn + wn*32 + j*16],
                                    acc[i][j], N, wmma::mem_row_major);
}

// ---------------- LIF over T on qkv -> q,k,v u8 spikes [t,b,h,n,d] ----------------
__global__ void k_lif_qkv(const float* __restrict__ qkv, const float* __restrict__ lw,
                          unsigned char* __restrict__ q, unsigned char* __restrict__ k,
                          unsigned char* __restrict__ vv){
    int idx = blockIdx.x*blockDim.x + threadIdx.x;
    if (idx >= BNROWS*3*CC) return;
    int j = idx % (3*CC); int bn = idx / (3*CC);
    int i = j / CC; int jj = j - i*CC; int hh = jj >> 6; int dd = jj & 63;
    float decay = sigmoidf_(lw[2 + i]);
    unsigned char* outp = (i == 0) ? q : (i == 1) ? k : vv;
    int b = bn >> 8, n = bn & 255;
    float v = 0.f;
#pragma unroll
    for (int t = 0; t < TT; t++){
        float val = qkv[((size_t)t*BNROWS + bn)*(3*CC) + j];
        v += (val - v)*decay;
        unsigned char s = (v >= 1.f);
        outp[((((size_t)t*BB + b)*NHEAD + hh)*NN + n)*DH + dd] = s;
        if (s) v = 0.f;
    }
}

// ---------------- kv = k^T v via ballot-packed popc (exact int) ----------------
__global__ void __launch_bounds__(256) k_kv(const unsigned char* __restrict__ kk,
                                            const unsigned char* __restrict__ vv,
                                            float* __restrict__ kvout){
    __shared__ unsigned int kb[DH][8], vb[DH][8];
    int tbh = blockIdx.x;
    int tid = threadIdx.x, warp = tid >> 5, lane = tid & 31;
    size_t base = (size_t)tbh*NN*DH;
    for (int w = warp; w < 1024; w += 8){
        int op = w >> 9;
        int r = w & 511; int d = r >> 3; int wg = r & 7;
        const unsigned char* src = op ? vv : kk;
        unsigned char val = src[base + (size_t)(wg*32 + lane)*DH + d];
        unsigned int m = __ballot_sync(0xffffffffu, val != 0);
        if (lane == 0) (op ? vb : kb)[d][wg] = m;
    }
    __syncthreads();
    for (int o = tid; o < DH*DH; o += 256){
        int d = o >> 6, e = o & 63;
        int c = 0;
#pragma unroll
        for (int w = 0; w < 8; w++) c += __popc(kb[d][w] & vb[e][w]);
        kvout[(size_t)tbh*DH*DH + o] = (float)c;
    }
}

// ---------------- a = (q @ kv) * scale, written as [t,b,n,C] ----------------
__global__ void __launch_bounds__(256) k_attn_a(const unsigned char* __restrict__ q,
                                                const float* __restrict__ kvin,
                                                float* __restrict__ a){
    __shared__ float skv[DH][DH];
    __shared__ unsigned int sq[NN][2];
    int tbh = blockIdx.x;
    int tid = threadIdx.x, warp = tid >> 5, lane = tid & 31;
    size_t qbase = (size_t)tbh*NN*DH;
    for (int o = tid; o < DH*DH; o += 256)
        skv[o >> 6][o & 63] = kvin[(size_t)tbh*DH*DH + o];
    for (int w = warp; w < 512; w += 8){
        int n = w >> 1, gidx = w & 1;
        unsigned char val = q[qbase + (size_t)n*DH + gidx*32 + lane];
        unsigned int m = __ballot_sync(0xffffffffu, val != 0);
        if (lane == 0) sq[n][gidx] = m;
    }
    __syncthreads();
    int hh = tbh & 7; int tb = tbh >> 3;
    int e = tid & 63, n0 = tid >> 6;
    for (int n = n0; n < NN; n += 4){
        unsigned int m0 = sq[n][0], m1 = sq[n][1];
        float acc = 0.f;
#pragma unroll
        for (int d = 0; d < 32; d++) if (m0 & (1u << d)) acc += skv[d][e];
#pragma unroll
        for (int d = 0; d < 32; d++) if (m1 & (1u << d)) acc += skv[d + 32][e];
        a[((size_t)tb*NN + n)*CC + hh*DH + e] = acc * 0.125f;  // scale = 64^-0.5
    }
}

// ---------------- generic LIF over T on fp32 [T,R] (+optional per-col bias) -> bf16 spikes ----------------
__global__ void k_lif_elem(const float* __restrict__ in, const float* __restrict__ bias, int nc,
                           const float* __restrict__ lw, int lwi,
                           __nv_bfloat16* __restrict__ out, int R){
    int i = blockIdx.x*blockDim.x + threadIdx.x;
    if (i >= R) return;
    float decay = sigmoidf_(lw[lwi]);
    float bv = bias ? bias[i % nc] : 0.f;
    float v = 0.f;
#pragma unroll
    for (int t = 0; t < TT; t++){
        float val = in[(size_t)t*R + i] + bv;
        v += (val - v)*decay;
        float s = (v >= 1.f) ? 1.f : 0.f;
        out[(size_t)t*R + i] = __float2bfloat16(s);
        if (s > 0.f) v = 0.f;
    }
}

// ---------------- final: out[t,b,c,h,w] = xt + fc2_out + fc2_b (transposed) ----------------
__global__ void k_out(const float* __restrict__ xt, const float* __restrict__ tmp,
                      const float* __restrict__ fb, float* __restrict__ out){
    __shared__ float tile[32][33];
    int tb = blockIdx.z; int n0 = blockIdx.x*32, c0 = blockIdx.y*32;
    int tx = threadIdx.x, ty = threadIdx.y;
    size_t ib = (size_t)tb*NN*CC;
    float bb = fb[c0 + tx];
#pragma unroll
    for (int j = 0; j < 32; j += 8){
        size_t idx = ib + (size_t)(n0 + ty + j)*CC + c0 + tx;
        tile[ty + j][tx] = xt[idx] + tmp[idx] + bb;
    }
    __syncthreads();
    size_t ob = (size_t)tb*CC*NN;
#pragma unroll
    for (int j = 0; j < 32; j += 8)
        out[ob + (size_t)(c0 + ty + j)*NN + n0 + tx] = tile[tx][ty + j];
}

// ---------------- launch ----------------
extern "C" void kernel_launch(void* const* d_in, const int* in_sizes, int n_in,
                              void* d_out, int out_size){
    const float* x      = (const float*)d_in[0];
    const float* conv_w = (const float*)d_in[1];
    const float* conv_b = (const float*)d_in[2];
    const float* ln1_g  = (const float*)d_in[3];
    const float* ln1_b  = (const float*)d_in[4];
    const float* qkv_w  = (const float*)d_in[5];
    const float* proj_w = (const float*)d_in[6];
    const float* proj_b = (const float*)d_in[7];
    const float* ln2_g  = (const float*)d_in[8];
    const float* ln2_b  = (const float*)d_in[9];
    const float* fc1_w  = (const float*)d_in[10];
    const float* fc1_b  = (const float*)d_in[11];
    const float* fc2_w  = (const float*)d_in[12];
    const float* fc2_b  = (const float*)d_in[13];
    const float* lif_w  = (const float*)d_in[14];
    float* out = (float*)d_out;

    void *p_xt, *p_qkv, *p_ff, *p_a, *p_tmp, *p_kv, *p_s1, *p_q, *p_k, *p_v,
         *p_h, *p_h4, *p_wq, *p_wp, *p_w1, *p_w2;
    cudaGetSymbolAddress(&p_xt,  g_xt);
    cudaGetSymbolAddress(&p_qkv, g_qkv);
    cudaGetSymbolAddress(&p_ff,  g_ff);
    cudaGetSymbolAddress(&p_a,   g_a);
    cudaGetSymbolAddress(&p_tmp, g_tmp);
    cudaGetSymbolAddress(&p_kv,  g_kv);
    cudaGetSymbolAddress(&p_s1,  g_s1);
    cudaGetSymbolAddress(&p_q,   g_q);
    cudaGetSymbolAddress(&p_k,   g_k);
    cudaGetSymbolAddress(&p_v,   g_v);
    cudaGetSymbolAddress(&p_h,   g_h);
    cudaGetSymbolAddress(&p_h4,  g_h4);
    cudaGetSymbolAddress(&p_wq,  g_wq);
    cudaGetSymbolAddress(&p_wp,  g_wp);
    cudaGetSymbolAddress(&p_w1,  g_w1);
    cudaGetSymbolAddress(&p_w2,  g_w2);

    float* xt   = (float*)p_xt;
    float* qkv  = (float*)p_qkv;
    float* ff   = (float*)p_ff;
    float* av   = (float*)p_a;
    float* tmp  = (float*)p_tmp;
    float* kvb  = (float*)p_kv;
    unsigned char* s1 = (unsigned char*)p_s1;
    unsigned char* qs = (unsigned char*)p_q;
    unsigned char* ks = (unsigned char*)p_k;
    unsigned char* vs = (unsigned char*)p_v;
    __nv_bfloat16* h  = (__nv_bfloat16*)p_h;
    __nv_bfloat16* h4 = (__nv_bfloat16*)p_h4;
    __nv_bfloat16* wq = (__nv_bfloat16*)p_wq;
    __nv_bfloat16* wp = (__nv_bfloat16*)p_wp;
    __nv_bfloat16* w1 = (__nv_bfloat16*)p_w1;
    __nv_bfloat16* w2 = (__nv_bfloat16*)p_w2;

    // weight conversion to bf16
    k_cvt_bf16<<<(3*CC*CC + 255)/256, 256>>>(qkv_w, wq, 3*CC*CC);
    k_cvt_bf16<<<(CC*CC   + 255)/256, 256>>>(proj_w, wp, CC*CC);
    k_cvt_bf16<<<(HID*CC  + 255)/256, 256>>>(fc1_w, w1, HID*CC);
    k_cvt_bf16<<<(CC*HID  + 255)/256, 256>>>(fc2_w, w2, CC*HID);

    // 1) LIF on x
    k_lif1<<<PLANE/256, 256>>>(x, lif_w, s1);
    // 2) depthwise conv + residual (NCHW), y stored in g_ff scratch
    k_conv<<<(TT*PLANE)/256, 256>>>(x, s1, conv_w, conv_b, ff);
    // 3) transpose -> xt [t,b,n,c]
    k_transpose<<<dim3(NN/32, CC/32, TT*BB), dim3(32,8)>>>(ff, xt);
    // 4) LN1 + LIF -> h1
    k_ln_lif<<<BNROWS, 256>>>(xt, ln1_g, ln1_b, lif_w, 1, nullptr, nullptr, h);
    // 5) QKV GEMM
    k_gemm_bf16<<<dim3(3*CC/GBN, MROWS/GBM), 256>>>(h, wq, qkv, MROWS, 3*CC, CC);
    // 6) LIF on qkv -> q,k,v spikes
    k_lif_qkv<<<(BNROWS*3*CC)/256, 256>>>(qkv, lif_w, qs, ks, vs);
    // 7) kv = k^T v (popc)
    k_kv<<<TT*BB*NHEAD, 256>>>(ks, vs, kvb);
    // 8) a = q @ kv * scale
    k_attn_a<<<TT*BB*NHEAD, 256>>>(qs, kvb, av);
    // 9) LIF on a -> spikes (reuse h)
    k_lif_elem<<<(BNROWS*CC)/256, 256>>>(av, nullptr, 1, lif_w, 5, h, BNROWS*CC);
    // 10) proj GEMM -> tmp
    k_gemm_bf16<<<dim3(CC/GBN, MROWS/GBM), 256>>>(h, wp, tmp, MROWS, CC, CC);
    // 11) xt += tmp + proj_b; LN2 + LIF -> h3
    k_ln_lif<<<BNROWS, 256>>>(xt, ln2_g, ln2_b, lif_w, 6, tmp, proj_b, h);
    // 12) FC1 GEMM -> ff
    k_gemm_bf16<<<dim3(HID/GBN, MROWS/GBM), 256>>>(h, w1, ff, MROWS, HID, CC);
    // 13) LIF on ff (+fc1_b) -> h4
    k_lif_elem<<<(BNROWS*HID)/256, 256>>>(ff, fc1_b, HID, lif_w, 7, h4, BNROWS*HID);
    // 14) FC2 GEMM -> tmp
    k_gemm_bf16<<<dim3(CC/GBN, MROWS/GBM), 256>>>(h4, w2, tmp, MROWS, CC, HID);
    // 15) out = transpose(xt + tmp + fc2_b)
    k_out<<<dim3(NN/32, CC/32, TT*BB), dim3(32,8)>>>(xt, tmp, fc2_b, out);
}